// round 2
// baseline (speedup 1.0000x reference)
#include <cuda_runtime.h>
#include <math.h>

// Problem dims
#define BB 256
#define DD 128
#define FF 8
#define TT 128
#define HH 128
#define KDIM (DD*FF)        // 1024
#define G4H (4*HH)          // 512

// Scratch (device globals; no allocation allowed)
__device__ float g_ex[BB*DD];
__device__ float g_a[BB*DD];
__device__ float g_y[BB*TT*G4H];   // y[b][t][g], 64 MB

// ---------------------------------------------------------------------------
// K1: ex[b,d] = sum_{f,t} input[b,d,f,t] * w_x[f*T+t]; one warp per (b,d)
// ---------------------------------------------------------------------------
__global__ void k1_ex(const float* __restrict__ input, const float* __restrict__ w_attn) {
    const float* w_x = w_attn + 2*HH;            // w_attn[2H:] length 1024
    int warp = (blockIdx.x * blockDim.x + threadIdx.x) >> 5;
    int lane = threadIdx.x & 31;
    if (warp >= BB*DD) return;
    const float* base = input + (size_t)warp * KDIM;   // contiguous 1024 floats
    float s = 0.f;
    #pragma unroll 8
    for (int i = 0; i < KDIM/32; i++) {
        int idx = lane + 32*i;
        s += base[idx] * __ldg(&w_x[idx]);
    }
    #pragma unroll
    for (int o = 16; o > 0; o >>= 1) s += __shfl_down_sync(0xffffffffu, s, o);
    if (lane == 0) g_ex[warp] = s;
}

// ---------------------------------------------------------------------------
// K1b: a[b,:] = softmax(ex[b,:]) over D=128. One block (128 thr) per batch.
// ---------------------------------------------------------------------------
__global__ void k1b_softmax() {
    __shared__ float red[4];
    int b = blockIdx.x;
    int d = threadIdx.x;            // 128 threads
    int lane = d & 31, w = d >> 5;
    float v = g_ex[b*DD + d];
    // max
    float m = v;
    #pragma unroll
    for (int o = 16; o > 0; o >>= 1) m = fmaxf(m, __shfl_xor_sync(0xffffffffu, m, o));
    if (lane == 0) red[w] = m;
    __syncthreads();
    m = fmaxf(fmaxf(red[0], red[1]), fmaxf(red[2], red[3]));
    float e = expf(v - m);
    // sum
    float s = e;
    #pragma unroll
    for (int o = 16; o > 0; o >>= 1) s += __shfl_xor_sync(0xffffffffu, s, o);
    __syncthreads();
    if (lane == 0) red[w] = s;
    __syncthreads();
    s = red[0] + red[1] + red[2] + red[3];
    g_a[b*DD + d] = e / s;
}

// ---------------------------------------------------------------------------
// K2: y[b][t][g] = sum_k (a[b,k>>3] * X_b[k][t]) * W_ih[g][k]
//     X_b[k][t] = input[(b*1024 + k)*128 + t]
//     Per CTA: one b, g-tile of 128, all 128 t.  Tile 128(t) x 128(g), BK=16.
//     256 threads, 8x8 microtile. Output row-major in (t, g) -> coalesced.
// ---------------------------------------------------------------------------
#define BK 16
__global__ __launch_bounds__(256) void k2_gemm(const float* __restrict__ input,
                                               const float* __restrict__ W_ih) {
    int b = blockIdx.y;
    int gbase = blockIdx.x * 128;
    __shared__ float As[BK][128];      // As[kk][t]  (scaled X)
    __shared__ float Bs[BK][128];      // Bs[kk][g]  (W transposed)
    __shared__ float a_sm[DD];
    int tid = threadIdx.x;
    if (tid < DD) a_sm[tid] = g_a[b*DD + tid];
    __syncthreads();
    int tx = tid & 15;                 // g dir, 16 lanes * 8 (stride 16)
    int ty = tid >> 4;                 // t dir, 16 * 8 rows
    float acc[8][8];
    #pragma unroll
    for (int i = 0; i < 8; i++)
        #pragma unroll
        for (int j = 0; j < 8; j++) acc[i][j] = 0.f;

    const float* Xb = input + (size_t)b * KDIM * TT;

    for (int k0 = 0; k0 < KDIM; k0 += BK) {
        // load A tile: 16 k-rows x 128 t, scaled by a[b, k>>3]
        {
            int r  = tid >> 5;              // 0..7
            int t4 = (tid & 31) * 4;
            #pragma unroll
            for (int p = 0; p < 2; p++) {
                int rr = r + p*8;
                float4 v = *(const float4*)(Xb + (size_t)(k0 + rr)*TT + t4);
                float s = a_sm[(k0 + rr) >> 3];
                float4 o; o.x = v.x*s; o.y = v.y*s; o.z = v.z*s; o.w = v.w*s;
                *(float4*)&As[rr][t4] = o;
            }
        }
        // load B tile transposed: Bs[kk][g] = W_ih[gbase+g][k0+kk]
        {
            int gl = tid >> 2;              // 0..63
            int kq = (tid & 3) * 4;
            #pragma unroll
            for (int p = 0; p < 2; p++) {
                int gg = gl + p*64;
                float4 v = *(const float4*)(W_ih + (size_t)(gbase+gg)*KDIM + k0 + kq);
                Bs[kq+0][gg] = v.x; Bs[kq+1][gg] = v.y;
                Bs[kq+2][gg] = v.z; Bs[kq+3][gg] = v.w;
            }
        }
        __syncthreads();
        #pragma unroll
        for (int kk = 0; kk < BK; kk++) {
            float rA[8], rB[8];
            float4 a0 = *(const float4*)&As[kk][ty*8];
            float4 a1 = *(const float4*)&As[kk][ty*8+4];
            rA[0]=a0.x; rA[1]=a0.y; rA[2]=a0.z; rA[3]=a0.w;
            rA[4]=a1.x; rA[5]=a1.y; rA[6]=a1.z; rA[7]=a1.w;
            #pragma unroll
            for (int j = 0; j < 8; j++) rB[j] = Bs[kk][tx + 16*j];
            #pragma unroll
            for (int i = 0; i < 8; i++)
                #pragma unroll
                for (int j = 0; j < 8; j++) acc[i][j] += rA[i]*rB[j];
        }
        __syncthreads();
    }
    // write: y[(b*T + t)*512 + gbase + g], g strided by 16 across lanes -> coalesced
    #pragma unroll
    for (int i = 0; i < 8; i++) {
        int t = ty*8 + i;
        float* yrow = g_y + ((size_t)(b*TT + t))*G4H + gbase;
        #pragma unroll
        for (int j = 0; j < 8; j++) yrow[tx + 16*j] = acc[i][j];
    }
}

// ---------------------------------------------------------------------------
// K3: persistent recurrence. 128 CTAs x 512 threads, 2 batches per CTA.
//     W_hh rows [0, SMEM_W_ROWS) cached in smem fp32, rest streamed from L2.
// ---------------------------------------------------------------------------
#define SMEM_W_ROWS 432

__device__ __forceinline__ float sigm(float x) { return 1.f / (1.f + expf(-x)); }

__global__ __launch_bounds__(512) void k3_lstm(const float* __restrict__ W_hh,
                                               const float* __restrict__ b_ih,
                                               const float* __restrict__ b_hh,
                                               float* __restrict__ out) {
    extern __shared__ float sm[];
    float* Ws   = sm;                          // SMEM_W_ROWS * 128
    float* hs   = Ws + SMEM_W_ROWS*HH;         // 2*128
    float* cs   = hs + 2*HH;                   // 2*128
    float* gs   = cs + 2*HH;                   // 2*512
    float* bias = gs + 2*G4H;                  // 512

    int tid = threadIdx.x;                     // 512
    int b0 = blockIdx.x * 2;

    for (int i = tid; i < SMEM_W_ROWS*HH/4; i += 512)
        ((float4*)Ws)[i] = ((const float4*)W_hh)[i];
    bias[tid] = b_ih[tid] + b_hh[tid];
    if (tid < 2*HH) { hs[tid] = 0.f; cs[tid] = 0.f; }
    __syncthreads();

    const int g = tid;
    const int L = g & 31;
    const float* wrow = (g < SMEM_W_ROWS) ? (Ws + g*HH) : (W_hh + (size_t)g*HH);
    const float* h0 = hs, *h1 = hs + HH;
    const float myBias = bias[g];

    for (int t = 0; t < TT; t++) {
        float acc0a = g_y[((size_t)(b0*TT + t))*G4H + g] + myBias;
        float acc1a = g_y[((size_t)((b0+1)*TT + t))*G4H + g] + myBias;
        float acc0b = 0.f, acc1b = 0.f;
        #pragma unroll
        for (int i = 0; i < 32; i += 2) {
            int k0 = 4*((L + i) & 31);
            int k1 = 4*((L + i + 1) & 31);
            float4 w0 = *(const float4*)(wrow + k0);
            float4 x0 = *(const float4*)(h0 + k0);
            float4 y0 = *(const float4*)(h1 + k0);
            acc0a += w0.x*x0.x + w0.y*x0.y + w0.z*x0.z + w0.w*x0.w;
            acc1a += w0.x*y0.x + w0.y*y0.y + w0.z*y0.z + w0.w*y0.w;
            float4 w1 = *(const float4*)(wrow + k1);
            float4 x1 = *(const float4*)(h0 + k1);
            float4 y1 = *(const float4*)(h1 + k1);
            acc0b += w1.x*x1.x + w1.y*x1.y + w1.z*x1.z + w1.w*x1.w;
            acc1b += w1.x*y1.x + w1.y*y1.y + w1.z*y1.z + w1.w*y1.w;
        }
        gs[g]       = acc0a + acc0b;
        gs[G4H + g] = acc1a + acc1b;
        __syncthreads();
        if (tid < 2*HH) {
            int bb = tid >> 7;          // 0/1
            int j  = tid & (HH-1);
            const float* G = gs + bb*G4H;
            float iv = G[j], fv = G[HH + j], gv = G[2*HH + j], ov = G[3*HH + j];
            float c  = cs[bb*HH + j];
            float cn = sigm(fv)*c + sigm(iv)*tanhf(gv);
            float hn = sigm(ov)*tanhf(cn);
            cs[bb*HH + j] = cn;
            hs[bb*HH + j] = hn;
            out[((size_t)(b0+bb)*TT + t)*HH + j] = hn;
        }
        __syncthreads();
    }
}

// ---------------------------------------------------------------------------
extern "C" void kernel_launch(void* const* d_in, const int* in_sizes, int n_in,
                              void* d_out, int out_size) {
    const float* input  = (const float*)d_in[0];  // (B,D,F,T)
    const float* w_attn = (const float*)d_in[1];  // (F*T + 2H,)
    // d_in[2] = b_attn (unused: softmax is shift-invariant)
    const float* W_ih   = (const float*)d_in[3];  // (4H, D*F)
    const float* W_hh   = (const float*)d_in[4];  // (4H, H)
    const float* b_ih   = (const float*)d_in[5];  // (4H,)
    const float* b_hh   = (const float*)d_in[6];  // (4H,)
    float* out = (float*)d_out;                   // (B, T, H)

    // K1: ex (one warp per (b,d)); 32768 warps -> 4096 blocks x 256
    k1_ex<<<4096, 256>>>(input, w_attn);
    // K1b: softmax over D per batch
    k1b_softmax<<<BB, DD>>>();
    // K2: batched input-projection GEMM
    {
        dim3 grid(4, BB);
        k2_gemm<<<grid, 256>>>(input, W_ih);
    }
    // K3: persistent LSTM recurrence
    {
        int smem = (SMEM_W_ROWS*HH + 2*HH + 2*HH + 2*G4H + G4H) * (int)sizeof(float);
        cudaFuncSetAttribute(k3_lstm, cudaFuncAttributeMaxDynamicSharedMemorySize, smem);
        k3_lstm<<<BB/2, 512, smem>>>(W_hh, b_ih, b_hh, out);
    }
}

// round 3
// speedup vs baseline: 1.1092x; 1.1092x over previous
#include <cuda_runtime.h>
#include <math.h>

// Problem dims
#define BB 256
#define DD 128
#define FF 8
#define TT 128
#define HH 128
#define KDIM (DD*FF)        // 1024
#define G4H (4*HH)          // 512

// Scratch (device globals; no allocation allowed)
__device__ float g_ex[BB*DD];
__device__ float g_a[BB*DD];
__device__ float g_y[BB*TT*G4H];   // y[b][t][g], 64 MB

// packed f32x2 FMA (sm_100+): d = a*b + c elementwise on 2 packed floats
#define FMA_F32X2(d, a, b, c) \
    asm("fma.rn.f32x2 %0, %1, %2, %3;" : "=l"(d) : "l"(a), "l"(b), "l"(c))

__device__ __forceinline__ float f32x2_lo(unsigned long long v) {
    return __uint_as_float((unsigned)(v & 0xffffffffull));
}
__device__ __forceinline__ float f32x2_hi(unsigned long long v) {
    return __uint_as_float((unsigned)(v >> 32));
}

// ---------------------------------------------------------------------------
// K1: ex[b,d] = sum_{f,t} input[b,d,f,t] * w_x[f*T+t]; one warp per (b,d)
// ---------------------------------------------------------------------------
__global__ void k1_ex(const float* __restrict__ input, const float* __restrict__ w_attn) {
    const float* w_x = w_attn + 2*HH;            // w_attn[2H:] length 1024
    int warp = (blockIdx.x * blockDim.x + threadIdx.x) >> 5;
    int lane = threadIdx.x & 31;
    if (warp >= BB*DD) return;
    const float* base = input + (size_t)warp * KDIM;   // contiguous 1024 floats
    float s = 0.f;
    #pragma unroll 8
    for (int i = 0; i < KDIM/32; i++) {
        int idx = lane + 32*i;
        s += base[idx] * __ldg(&w_x[idx]);
    }
    #pragma unroll
    for (int o = 16; o > 0; o >>= 1) s += __shfl_down_sync(0xffffffffu, s, o);
    if (lane == 0) g_ex[warp] = s;
}

// ---------------------------------------------------------------------------
// K1b: a[b,:] = softmax(ex[b,:]) over D=128. One block (128 thr) per batch.
// ---------------------------------------------------------------------------
__global__ void k1b_softmax() {
    __shared__ float red[4];
    int b = blockIdx.x;
    int d = threadIdx.x;            // 128 threads
    int lane = d & 31, w = d >> 5;
    float v = g_ex[b*DD + d];
    float m = v;
    #pragma unroll
    for (int o = 16; o > 0; o >>= 1) m = fmaxf(m, __shfl_xor_sync(0xffffffffu, m, o));
    if (lane == 0) red[w] = m;
    __syncthreads();
    m = fmaxf(fmaxf(red[0], red[1]), fmaxf(red[2], red[3]));
    float e = expf(v - m);
    float s = e;
    #pragma unroll
    for (int o = 16; o > 0; o >>= 1) s += __shfl_xor_sync(0xffffffffu, s, o);
    __syncthreads();
    if (lane == 0) red[w] = s;
    __syncthreads();
    s = red[0] + red[1] + red[2] + red[3];
    g_a[b*DD + d] = e / s;
}

// ---------------------------------------------------------------------------
// K2: y[b][t][g] = sum_k (a[b,k>>3] * X_b[k][t]) * W_ih[g][k]
//     f32x2 packed-FMA variant. 256 threads, tile 128(t) x 128(g), BK=16.
//     A stored DUPLICATED (v,v) in smem so the FMA2 a-operand needs no packing.
//     Thread microtile: 8 t (ty*8..) x 8 contiguous g (tx*8..) = 32 f32x2 accs.
// ---------------------------------------------------------------------------
#define BK 16
__global__ __launch_bounds__(256) void k2_gemm(const float* __restrict__ input,
                                               const float* __restrict__ W_ih) {
    int b = blockIdx.y;
    int gbase = blockIdx.x * 128;
    __shared__ unsigned long long As2[BK*128];   // As2[kk*128+t] = (v,v) packed, 16KB
    __shared__ float Bs[BK][128];                // Bs[kk][g], 8KB
    __shared__ float a_sm[DD];
    int tid = threadIdx.x;
    if (tid < DD) a_sm[tid] = g_a[b*DD + tid];
    __syncthreads();
    int tx = tid & 15;                 // g strip: g = tx*8 .. tx*8+7 (contiguous)
    int ty = tid >> 4;                 // t strip: t = ty*8 .. ty*8+7

    unsigned long long acc[8][4];
    #pragma unroll
    for (int i = 0; i < 8; i++)
        #pragma unroll
        for (int j = 0; j < 4; j++) acc[i][j] = 0ull;

    const float* Xb = input + (size_t)b * KDIM * TT;

    for (int k0 = 0; k0 < KDIM; k0 += BK) {
        // load A tile: 16 k-rows x 128 t, scaled, duplicated
        {
            int r  = tid >> 5;              // 0..7
            int t4 = (tid & 31) * 4;
            #pragma unroll
            for (int p = 0; p < 2; p++) {
                int rr = r + p*8;
                float4 v = *(const float4*)(Xb + (size_t)(k0 + rr)*TT + t4);
                float s = a_sm[(k0 + rr) >> 3];
                float4* dst = (float4*)&As2[rr*128 + t4];
                dst[0] = make_float4(v.x*s, v.x*s, v.y*s, v.y*s);
                dst[1] = make_float4(v.z*s, v.z*s, v.w*s, v.w*s);
            }
        }
        // load B tile transposed: Bs[kk][g] = W_ih[gbase+g][k0+kk]
        {
            int gl = tid >> 2;              // 0..63
            int kq = (tid & 3) * 4;
            #pragma unroll
            for (int p = 0; p < 2; p++) {
                int gg = gl + p*64;
                float4 v = *(const float4*)(W_ih + (size_t)(gbase+gg)*KDIM + k0 + kq);
                Bs[kq+0][gg] = v.x; Bs[kq+1][gg] = v.y;
                Bs[kq+2][gg] = v.z; Bs[kq+3][gg] = v.w;
            }
        }
        __syncthreads();
        #pragma unroll
        for (int kk = 0; kk < BK; kk++) {
            // a-dup: 8 duplicated t-values = 4x LDS.128 (broadcast within half-warp)
            unsigned long long ad[8];
            {
                const ulonglong2* src = (const ulonglong2*)&As2[kk*128 + ty*8];
                #pragma unroll
                for (int q = 0; q < 4; q++) {
                    ulonglong2 v = src[q];
                    ad[2*q] = v.x; ad[2*q+1] = v.y;
                }
            }
            // b pairs: 8 contiguous g = 4 f32x2 = 2x LDS.128
            unsigned long long bp[4];
            {
                const ulonglong2* src = (const ulonglong2*)&Bs[kk][tx*8];
                ulonglong2 v0 = src[0], v1 = src[1];
                bp[0] = v0.x; bp[1] = v0.y; bp[2] = v1.x; bp[3] = v1.y;
            }
            #pragma unroll
            for (int i = 0; i < 8; i++)
                #pragma unroll
                for (int j = 0; j < 4; j++)
                    FMA_F32X2(acc[i][j], ad[i], bp[j], acc[i][j]);
        }
        __syncthreads();
    }
    // write: thread owns contiguous 8 g -> 2 STG.128 per row
    #pragma unroll
    for (int i = 0; i < 8; i++) {
        int t = ty*8 + i;
        float* yrow = g_y + ((size_t)(b*TT + t))*G4H + gbase + tx*8;
        float f[8];
        #pragma unroll
        for (int j = 0; j < 4; j++) {
            f[2*j]   = f32x2_lo(acc[i][j]);
            f[2*j+1] = f32x2_hi(acc[i][j]);
        }
        *(float4*)(yrow)     = make_float4(f[0], f[1], f[2], f[3]);
        *(float4*)(yrow + 4) = make_float4(f[4], f[5], f[6], f[7]);
    }
}

// ---------------------------------------------------------------------------
// K3: persistent recurrence. 128 CTAs x 512 threads, 2 batches per CTA.
//     k in [0,64): W row in registers (16 float4).
//     k in [64,128): W in smem, pitch 68 floats (68 mod 32 = 4 -> conflict-free
//     float4 phases). h read as pure broadcasts (all lanes same address).
// ---------------------------------------------------------------------------
#define WREG 64
#define WP_PITCH 68

__device__ __forceinline__ float sigm(float x) { return 1.f / (1.f + expf(-x)); }

__global__ __launch_bounds__(512, 1) void k3_lstm(const float* __restrict__ W_hh,
                                                  const float* __restrict__ b_ih,
                                                  const float* __restrict__ b_hh,
                                                  float* __restrict__ out) {
    extern __shared__ float sm[];
    float* Wp   = sm;                          // 512 * 68
    float* hs   = Wp + G4H*WP_PITCH;           // 2*128
    float* cs   = hs + 2*HH;                   // 2*128
    float* gs   = cs + 2*HH;                   // 2*512
    float* bias = gs + 2*G4H;                  // 512

    int tid = threadIdx.x;                     // 512
    int b0 = blockIdx.x * 2;
    const int g = tid;

    // coalesced fill of Wp: Wp[g][k-64] = W_hh[g][k], k in [64,128)
    for (int idx = tid; idx < G4H*(HH-WREG); idx += 512) {
        int gg = idx >> 6;           // /64
        int kk = idx & 63;
        Wp[gg*WP_PITCH + kk] = W_hh[(size_t)gg*HH + WREG + kk];
    }
    bias[tid] = b_ih[tid] + b_hh[tid];
    if (tid < 2*HH) { hs[tid] = 0.f; cs[tid] = 0.f; }

    // register half of W row: k in [0,64)
    float4 wr[16];
    #pragma unroll
    for (int i = 0; i < 16; i++)
        wr[i] = *(const float4*)(W_hh + (size_t)g*HH + 4*i);

    __syncthreads();

    const float myBias = bias[g];
    const float* wprow = Wp + g*WP_PITCH;
    const float* h0 = hs;
    const float* h1 = hs + HH;
    const float* y0p = g_y + ((size_t)b0*TT)*G4H + g;
    const float* y1p = g_y + ((size_t)(b0+1)*TT)*G4H + g;

    float yn0 = *y0p, yn1 = *y1p;     // prefetched y(t)

    for (int t = 0; t < TT; t++) {
        float acc0 = yn0 + myBias;
        float acc1 = yn1 + myBias;
        if (t + 1 < TT) {             // prefetch y(t+1), hidden under the dot
            yn0 = y0p[(size_t)(t+1)*G4H];
            yn1 = y1p[(size_t)(t+1)*G4H];
        }
        float acc0b = 0.f, acc1b = 0.f;
        // register-W section: k in [0,64), h reads are warp-broadcasts
        #pragma unroll
        for (int i = 0; i < 16; i++) {
            float4 w = wr[i];
            float4 a = *(const float4*)(h0 + 4*i);
            float4 bv = *(const float4*)(h1 + 4*i);
            acc0  += w.x*a.x + w.y*a.y;
            acc0b += w.z*a.z + w.w*a.w;
            acc1  += w.x*bv.x + w.y*bv.y;
            acc1b += w.z*bv.z + w.w*bv.w;
        }
        // smem-W section: k in [64,128)
        #pragma unroll
        for (int i = 0; i < 16; i++) {
            float4 w = *(const float4*)(wprow + 4*i);
            float4 a = *(const float4*)(h0 + WREG + 4*i);
            float4 bv = *(const float4*)(h1 + WREG + 4*i);
            acc0  += w.x*a.x + w.y*a.y;
            acc0b += w.z*a.z + w.w*a.w;
            acc1  += w.x*bv.x + w.y*bv.y;
            acc1b += w.z*bv.z + w.w*bv.w;
        }
        gs[g]       = acc0 + acc0b;
        gs[G4H + g] = acc1 + acc1b;
        __syncthreads();
        if (tid < 2*HH) {
            int bb = tid >> 7;          // 0/1
            int j  = tid & (HH-1);
            const float* G = gs + bb*G4H;
            float iv = G[j], fv = G[HH + j], gv = G[2*HH + j], ov = G[3*HH + j];
            float c  = cs[bb*HH + j];
            float cn = sigm(fv)*c + sigm(iv)*tanhf(gv);
            float hn = sigm(ov)*tanhf(cn);
            cs[bb*HH + j] = cn;
            hs[bb*HH + j] = hn;
            out[((size_t)(b0+bb)*TT + t)*HH + j] = hn;
        }
        __syncthreads();
    }
}

// ---------------------------------------------------------------------------
extern "C" void kernel_launch(void* const* d_in, const int* in_sizes, int n_in,
                              void* d_out, int out_size) {
    const float* input  = (const float*)d_in[0];  // (B,D,F,T)
    const float* w_attn = (const float*)d_in[1];  // (F*T + 2H,)
    // d_in[2] = b_attn (unused: softmax is shift-invariant)
    const float* W_ih   = (const float*)d_in[3];  // (4H, D*F)
    const float* W_hh   = (const float*)d_in[4];  // (4H, H)
    const float* b_ih   = (const float*)d_in[5];  // (4H,)
    const float* b_hh   = (const float*)d_in[6];  // (4H,)
    float* out = (float*)d_out;                   // (B, T, H)

    k1_ex<<<4096, 256>>>(input, w_attn);
    k1b_softmax<<<BB, DD>>>();
    {
        dim3 grid(4, BB);
        k2_gemm<<<grid, 256>>>(input, W_ih);
    }
    {
        int smem = (G4H*WP_PITCH + 2*HH + 2*HH + 2*G4H + G4H) * (int)sizeof(float);
        cudaFuncSetAttribute(k3_lstm, cudaFuncAttributeMaxDynamicSharedMemorySize, smem);
        k3_lstm<<<BB/2, 512, smem>>>(W_hh, b_ih, b_hh, out);
    }
}

// round 6
// speedup vs baseline: 1.4926x; 1.3457x over previous
#include <cuda_runtime.h>
#include <cuda_bf16.h>
#include <math.h>
#include <stdint.h>

// Problem dims
#define BB 256
#define DD 128
#define FF 8
#define TT 128
#define HH 128
#define KDIM (DD*FF)        // 1024
#define G4H (4*HH)          // 512

// Scratch (device globals; no allocation allowed)
__device__ float g_ex[BB*DD];
__device__ float g_a[BB*DD];
__device__ __align__(256) float g_y[BB*TT*G4H];                    // y[b][t][g], 64 MB
__device__ __align__(256) __nv_bfloat16 g_xhi[(size_t)BB*TT*KDIM]; // [b][t][k] 64 MB
__device__ __align__(256) __nv_bfloat16 g_xlo[(size_t)BB*TT*KDIM]; // 64 MB
__device__ __align__(256) __nv_bfloat16 g_whi[G4H*KDIM];           // [g][k] 1 MB
__device__ __align__(256) __nv_bfloat16 g_wlo[G4H*KDIM];

// ---------------- baseline-PTX helpers (no arch-feature instructions) -------
__device__ __forceinline__ uint32_t smem_u32(const void* p) {
    uint32_t a;
    asm("{ .reg .u64 t; cvta.to.shared.u64 t, %1; cvt.u32.u64 %0, t; }" : "=r"(a) : "l"(p));
    return a;
}
#define SWZ(o) ((o) ^ (((o) >> 3) & 0x70))

#define CP_ASYNC16(dst, src) \
    asm volatile("cp.async.cg.shared.global [%0], [%1], 16;" :: "r"(dst), "l"(src))
#define CP_COMMIT() asm volatile("cp.async.commit_group;" ::: "memory")
#define CP_WAIT(n)  asm volatile("cp.async.wait_group %0;" :: "n"(n) : "memory")

#define LDSM_X4(r0, r1, r2, r3, a) \
    asm volatile("ldmatrix.sync.aligned.m8n8.x4.shared.b16 {%0,%1,%2,%3}, [%4];" \
        : "=r"(r0), "=r"(r1), "=r"(r2), "=r"(r3) : "r"(a))

#define MMA16816(d, a0, a1, a2, a3, b0, b1) \
    asm volatile("mma.sync.aligned.m16n8k16.row.col.f32.bf16.bf16.f32 " \
        "{%0,%1,%2,%3},{%4,%5,%6,%7},{%8,%9},{%0,%1,%2,%3};" \
        : "+f"((d)[0]), "+f"((d)[1]), "+f"((d)[2]), "+f"((d)[3]) \
        : "r"(a0), "r"(a1), "r"(a2), "r"(a3), "r"(b0), "r"(b1))

// ---------------------------------------------------------------------------
// K1: ex[b,d] = sum_{f,t} input[b,d,f,t] * w_x[f*T+t]; one warp per (b,d)
// ---------------------------------------------------------------------------
__global__ void k1_ex(const float* __restrict__ input, const float* __restrict__ w_attn) {
    const float* w_x = w_attn + 2*HH;
    int warp = (blockIdx.x * blockDim.x + threadIdx.x) >> 5;
    int lane = threadIdx.x & 31;
    if (warp >= BB*DD) return;
    const float* base = input + (size_t)warp * KDIM;
    float s = 0.f;
    #pragma unroll 8
    for (int i = 0; i < KDIM/32; i++) {
        int idx = lane + 32*i;
        s += base[idx] * __ldg(&w_x[idx]);
    }
    #pragma unroll
    for (int o = 16; o > 0; o >>= 1) s += __shfl_down_sync(0xffffffffu, s, o);
    if (lane == 0) g_ex[warp] = s;
}

// ---------------------------------------------------------------------------
// K1b: a[b,:] = softmax(ex[b,:]) over D=128
// ---------------------------------------------------------------------------
__global__ void k1b_softmax() {
    __shared__ float red[4];
    int b = blockIdx.x;
    int d = threadIdx.x;
    int lane = d & 31, w = d >> 5;
    float v = g_ex[b*DD + d];
    float m = v;
    #pragma unroll
    for (int o = 16; o > 0; o >>= 1) m = fmaxf(m, __shfl_xor_sync(0xffffffffu, m, o));
    if (lane == 0) red[w] = m;
    __syncthreads();
    m = fmaxf(fmaxf(red[0], red[1]), fmaxf(red[2], red[3]));
    float e = expf(v - m);
    float s = e;
    #pragma unroll
    for (int o = 16; o > 0; o >>= 1) s += __shfl_xor_sync(0xffffffffu, s, o);
    __syncthreads();
    if (lane == 0) red[w] = s;
    __syncthreads();
    s = red[0] + red[1] + red[2] + red[3];
    g_a[b*DD + d] = e / s;
}

// ---------------------------------------------------------------------------
// kW: split W_ih into bf16 hi/lo, [g][k] K-major
// ---------------------------------------------------------------------------
__global__ void k_wsplit(const float* __restrict__ W_ih) {
    int idx = blockIdx.x * 256 + threadIdx.x;
    if (idx >= G4H*KDIM/2) return;
    float2 v = ((const float2*)W_ih)[idx];
    __nv_bfloat16 h0 = __float2bfloat16(v.x), h1 = __float2bfloat16(v.y);
    __nv_bfloat16 l0 = __float2bfloat16(v.x - __bfloat162float(h0));
    __nv_bfloat16 l1 = __float2bfloat16(v.y - __bfloat162float(h1));
    ((uint32_t*)g_whi)[idx] = (uint32_t)__bfloat16_as_ushort(h0) | ((uint32_t)__bfloat16_as_ushort(h1) << 16);
    ((uint32_t*)g_wlo)[idx] = (uint32_t)__bfloat16_as_ushort(l0) | ((uint32_t)__bfloat16_as_ushort(l1) << 16);
}

// ---------------------------------------------------------------------------
// k_prep: xhat = a[b,k>>3] * input[b,k,t]; bf16 split; transpose to [b][t][k]
// ---------------------------------------------------------------------------
__global__ __launch_bounds__(256) void k_prep(const float* __restrict__ input) {
    __shared__ float tile[64][129];
    int b = blockIdx.y, k0 = blockIdx.x * 64;
    int tid = threadIdx.x;
    int lane = tid & 31, r = tid >> 5;
    #pragma unroll
    for (int it = 0; it < 8; it++) {
        int row = it*8 + r;
        const float4 v = *(const float4*)(input + ((size_t)b*KDIM + k0 + row)*TT + lane*4);
        float s = g_a[b*DD + ((k0 + row) >> 3)];
        tile[row][lane*4+0] = v.x*s;
        tile[row][lane*4+1] = v.y*s;
        tile[row][lane*4+2] = v.z*s;
        tile[row][lane*4+3] = v.w*s;
    }
    __syncthreads();
    int kk = lane * 2;
    #pragma unroll
    for (int it = 0; it < 16; it++) {
        int t = it*8 + r;
        float x0 = tile[kk][t], x1 = tile[kk+1][t];
        __nv_bfloat16 h0 = __float2bfloat16(x0), h1 = __float2bfloat16(x1);
        __nv_bfloat16 l0 = __float2bfloat16(x0 - __bfloat162float(h0));
        __nv_bfloat16 l1 = __float2bfloat16(x1 - __bfloat162float(h1));
        uint32_t hp = (uint32_t)__bfloat16_as_ushort(h0) | ((uint32_t)__bfloat16_as_ushort(h1) << 16);
        uint32_t lp = (uint32_t)__bfloat16_as_ushort(l0) | ((uint32_t)__bfloat16_as_ushort(l1) << 16);
        size_t base = (size_t)(b*TT + t)*(KDIM/2) + (k0 >> 1);
        ((uint32_t*)g_xhi)[base + lane] = hp;
        ((uint32_t*)g_xlo)[base + lane] = lp;
    }
}

// ---------------------------------------------------------------------------
// k2_mma: Y[t][g] = sum_k Xs[t,k]*W[g,k], bf16 mma.sync 3-pass split.
// CTA: 128t x 128g, 256 threads (8 warps 4x2; warp = 32t x 64g).
// K chunks of 64, cp.async double-buffered SW128-swizzled smem.
// ---------------------------------------------------------------------------
#define K2_BUF 65536
#define T_AHI 0
#define T_ALO 16384
#define T_BHI 32768
#define T_BLO 49152
#define K2_SMEM (2*K2_BUF)

__device__ __forceinline__ void k2_load_chunk(uint32_t dstbase, int b, int gbase,
                                              int k0, int tid) {
    const char* pxhi = (const char*)g_xhi;
    const char* pxlo = (const char*)g_xlo;
    const char* pwhi = (const char*)g_whi;
    const char* pwlo = (const char*)g_wlo;
    int r = tid >> 3, l8 = tid & 7;          // r: 0..31
    #pragma unroll
    for (int it = 0; it < 4; it++) {
        int row = it*32 + r;
        uint32_t sw = SWZ((uint32_t)(row*128 + l8*16));
        size_t aoff = ((size_t)(b*TT + row)*KDIM + k0)*2 + l8*16;
        size_t boff = ((size_t)(gbase + row)*KDIM + k0)*2 + l8*16;
        CP_ASYNC16(dstbase + T_AHI + sw, pxhi + aoff);
        CP_ASYNC16(dstbase + T_ALO + sw, pxlo + aoff);
        CP_ASYNC16(dstbase + T_BHI + sw, pwhi + boff);
        CP_ASYNC16(dstbase + T_BLO + sw, pwlo + boff);
    }
}

__global__ __launch_bounds__(256, 1) void k2_mma() {
    extern __shared__ char smem[];
    uint32_t sb = smem_u32(smem);
    int tid = threadIdx.x;
    int lane = tid & 31, wid = tid >> 5;
    int b = blockIdx.y, gbase = blockIdx.x * 128;
    int wt = wid & 3;        // t block: wt*32
    int wg = wid >> 2;       // g block: wg*64

    float acc[2][8][4];
    #pragma unroll
    for (int mi = 0; mi < 2; mi++)
        #pragma unroll
        for (int ni = 0; ni < 8; ni++)
            #pragma unroll
            for (int q = 0; q < 4; q++) acc[mi][ni][q] = 0.f;

    // per-lane fragment byte offsets (within a tile, pre-swizzle row/col parts)
    // A: row = wt*32 + mi*16 + (lane%16); colbyte = ks*32 + (lane/16)*16
    int a_row_base = wt*32 + (lane & 15);
    int a_col_lane = (lane >> 4) * 16;
    // B: row = wg*64 + pair*16 + (lane/16)*8 + (lane%8); colbyte = ks*32 + ((lane/8)%2)*16
    int b_row_base = wg*64 + ((lane >> 4) * 8) + (lane & 7);
    int b_col_lane = ((lane >> 3) & 1) * 16;

    k2_load_chunk(sb, b, gbase, 0, tid);
    CP_COMMIT();

    int buf = 0;
    for (int chunk = 0; chunk < 16; chunk++) {
        if (chunk < 15) {
            k2_load_chunk(sb + (buf ^ 1)*K2_BUF, b, gbase, (chunk+1)*64, tid);
            CP_COMMIT();
            CP_WAIT(1);
        } else {
            CP_WAIT(0);
        }
        __syncthreads();

        uint32_t base = sb + buf*K2_BUF;
        #pragma unroll
        for (int ks = 0; ks < 4; ks++) {
            uint32_t ah[2][4], al[2][4], bh[4][4], bl[4][4];
            #pragma unroll
            for (int mi = 0; mi < 2; mi++) {
                uint32_t off = SWZ((uint32_t)((a_row_base + mi*16)*128 + ks*32 + a_col_lane));
                LDSM_X4(ah[mi][0], ah[mi][1], ah[mi][2], ah[mi][3], base + T_AHI + off);
                LDSM_X4(al[mi][0], al[mi][1], al[mi][2], al[mi][3], base + T_ALO + off);
            }
            #pragma unroll
            for (int p = 0; p < 4; p++) {
                uint32_t off = SWZ((uint32_t)((b_row_base + p*16)*128 + ks*32 + b_col_lane));
                LDSM_X4(bh[p][0], bh[p][1], bh[p][2], bh[p][3], base + T_BHI + off);
                LDSM_X4(bl[p][0], bl[p][1], bl[p][2], bl[p][3], base + T_BLO + off);
            }
            #pragma unroll
            for (int mi = 0; mi < 2; mi++) {
                #pragma unroll
                for (int ni = 0; ni < 8; ni++) {
                    int p = ni >> 1, h = (ni & 1) * 2;
                    // hi*hi
                    MMA16816(acc[mi][ni], ah[mi][0], ah[mi][1], ah[mi][2], ah[mi][3],
                             bh[p][h], bh[p][h+1]);
                    // hi*lo
                    MMA16816(acc[mi][ni], ah[mi][0], ah[mi][1], ah[mi][2], ah[mi][3],
                             bl[p][h], bl[p][h+1]);
                    // lo*hi
                    MMA16816(acc[mi][ni], al[mi][0], al[mi][1], al[mi][2], al[mi][3],
                             bh[p][h], bh[p][h+1]);
                }
            }
        }
        __syncthreads();
        buf ^= 1;
    }

    // Epilogue: acc -> g_y. c0,c1: (row l/4, col (l%4)*2); c2,c3: row+8
    int r0 = wt*32 + (lane >> 2);
    int c0 = gbase + wg*64 + (lane & 3)*2;
    #pragma unroll
    for (int mi = 0; mi < 2; mi++) {
        #pragma unroll
        for (int ni = 0; ni < 8; ni++) {
            int row = r0 + mi*16;
            int col = c0 + ni*8;
            float* p0 = g_y + (size_t)(b*TT + row)*G4H + col;
            float* p1 = g_y + (size_t)(b*TT + row + 8)*G4H + col;
            *(float2*)p0 = make_float2(acc[mi][ni][0], acc[mi][ni][1]);
            *(float2*)p1 = make_float2(acc[mi][ni][2], acc[mi][ni][3]);
        }
    }
}

// ---------------------------------------------------------------------------
// K3: persistent recurrence (unchanged).
// ---------------------------------------------------------------------------
#define WREG 64
#define WP_PITCH 68

__device__ __forceinline__ float sigm(float x) { return 1.f / (1.f + expf(-x)); }

__global__ __launch_bounds__(512, 1) void k3_lstm(const float* __restrict__ W_hh,
                                                  const float* __restrict__ b_ih,
                                                  const float* __restrict__ b_hh,
                                                  float* __restrict__ out) {
    extern __shared__ float sm[];
    float* Wp   = sm;
    float* hs   = Wp + G4H*WP_PITCH;
    float* cs   = hs + 2*HH;
    float* gs   = cs + 2*HH;
    float* bias = gs + 2*G4H;

    int tid = threadIdx.x;
    int b0 = blockIdx.x * 2;
    const int g = tid;

    for (int idx = tid; idx < G4H*(HH-WREG); idx += 512) {
        int gg = idx >> 6;
        int kk = idx & 63;
        Wp[gg*WP_PITCH + kk] = W_hh[(size_t)gg*HH + WREG + kk];
    }
    bias[tid] = b_ih[tid] + b_hh[tid];
    if (tid < 2*HH) { hs[tid] = 0.f; cs[tid] = 0.f; }

    float4 wr[16];
    #pragma unroll
    for (int i = 0; i < 16; i++)
        wr[i] = *(const float4*)(W_hh + (size_t)g*HH + 4*i);

    __syncthreads();

    const float myBias = bias[g];
    const float* wprow = Wp + g*WP_PITCH;
    const float* h0 = hs;
    const float* h1 = hs + HH;
    const float* y0p = g_y + ((size_t)b0*TT)*G4H + g;
    const float* y1p = g_y + ((size_t)(b0+1)*TT)*G4H + g;

    float yn0 = *y0p, yn1 = *y1p;

    for (int t = 0; t < TT; t++) {
        float acc0 = yn0 + myBias;
        float acc1 = yn1 + myBias;
        if (t + 1 < TT) {
            yn0 = y0p[(size_t)(t+1)*G4H];
            yn1 = y1p[(size_t)(t+1)*G4H];
        }
        float acc0b = 0.f, acc1b = 0.f;
        #pragma unroll
        for (int i = 0; i < 16; i++) {
            float4 w = wr[i];
            float4 a = *(const float4*)(h0 + 4*i);
            float4 bv = *(const float4*)(h1 + 4*i);
            acc0  += w.x*a.x + w.y*a.y;
            acc0b += w.z*a.z + w.w*a.w;
            acc1  += w.x*bv.x + w.y*bv.y;
            acc1b += w.z*bv.z + w.w*bv.w;
        }
        #pragma unroll
        for (int i = 0; i < 16; i++) {
            float4 w = *(const float4*)(wprow + 4*i);
            float4 a = *(const float4*)(h0 + WREG + 4*i);
            float4 bv = *(const float4*)(h1 + WREG + 4*i);
            acc0  += w.x*a.x + w.y*a.y;
            acc0b += w.z*a.z + w.w*a.w;
            acc1  += w.x*bv.x + w.y*bv.y;
            acc1b += w.z*bv.z + w.w*bv.w;
        }
        gs[g]       = acc0 + acc0b;
        gs[G4H + g] = acc1 + acc1b;
        __syncthreads();
        if (tid < 2*HH) {
            int bb = tid >> 7;
            int j  = tid & (HH-1);
            const float* G = gs + bb*G4H;
            float iv = G[j], fv = G[HH + j], gv = G[2*HH + j], ov = G[3*HH + j];
            float c  = cs[bb*HH + j];
            float cn = sigm(fv)*c + sigm(iv)*tanhf(gv);
            float hn = sigm(ov)*tanhf(cn);
            cs[bb*HH + j] = cn;
            hs[bb*HH + j] = hn;
            out[((size_t)(b0+bb)*TT + t)*HH + j] = hn;
        }
        __syncthreads();
    }
}

// ---------------------------------------------------------------------------
extern "C" void kernel_launch(void* const* d_in, const int* in_sizes, int n_in,
                              void* d_out, int out_size) {
    const float* input  = (const float*)d_in[0];  // (B,D,F,T)
    const float* w_attn = (const float*)d_in[1];  // (F*T + 2H,)
    // d_in[2] = b_attn (unused: softmax is shift-invariant)
    const float* W_ih   = (const float*)d_in[3];  // (4H, D*F)
    const float* W_hh   = (const float*)d_in[4];  // (4H, H)
    const float* b_ih   = (const float*)d_in[5];  // (4H,)
    const float* b_hh   = (const float*)d_in[6];  // (4H,)
    float* out = (float*)d_out;                   // (B, T, H)

    k1_ex<<<4096, 256>>>(input, w_attn);
    k1b_softmax<<<BB, DD>>>();
    k_wsplit<<<(G4H*KDIM/2 + 255)/256, 256>>>(W_ih);
    {
        dim3 grid(KDIM/64, BB);
        k_prep<<<grid, 256>>>(input);
    }
    {
        cudaFuncSetAttribute(k2_mma, cudaFuncAttributeMaxDynamicSharedMemorySize, K2_SMEM);
        dim3 grid(G4H/128, BB);
        k2_mma<<<grid, 256, K2_SMEM>>>();
    }
    {
        int smem = (G4H*WP_PITCH + 2*HH + 2*HH + 2*G4H + G4H) * (int)sizeof(float);
        cudaFuncSetAttribute(k3_lstm, cudaFuncAttributeMaxDynamicSharedMemorySize, smem);
        k3_lstm<<<BB/2, 512, smem>>>(W_hh, b_ih, b_hh, out);
    }
}

// round 7
// speedup vs baseline: 2.1764x; 1.4581x over previous
#include <cuda_runtime.h>
#include <cuda_bf16.h>
#include <math.h>
#include <stdint.h>

// Problem dims
#define BB 256
#define DD 128
#define FF 8
#define TT 128
#define HH 128
#define KDIM (DD*FF)        // 1024
#define G4H (4*HH)          // 512

// Scratch (device globals; no allocation allowed)
__device__ float g_ex[BB*DD];
__device__ float g_a[BB*DD];
__device__ __align__(256) float g_y[BB*TT*G4H];                    // y[b][t][g], 64 MB
__device__ __align__(256) __nv_bfloat16 g_xhi[(size_t)BB*TT*KDIM]; // [b][t][k] 64 MB
__device__ __align__(256) __nv_bfloat16 g_xlo[(size_t)BB*TT*KDIM]; // 64 MB
__device__ __align__(256) __nv_bfloat16 g_whi[G4H*KDIM];           // [g][k] 1 MB
__device__ __align__(256) __nv_bfloat16 g_wlo[G4H*KDIM];

// ---------------- baseline-PTX helpers ----------------
__device__ __forceinline__ uint32_t smem_u32(const void* p) {
    uint32_t a;
    asm("{ .reg .u64 t; cvta.to.shared.u64 t, %1; cvt.u32.u64 %0, t; }" : "=r"(a) : "l"(p));
    return a;
}
#define SWZ64(o) ((o) ^ (((o) >> 3) & 0x30))

#define CP_ASYNC16(dst, src) \
    asm volatile("cp.async.cg.shared.global [%0], [%1], 16;" :: "r"(dst), "l"(src))
#define CP_COMMIT() asm volatile("cp.async.commit_group;" ::: "memory")
#define CP_WAIT(n)  asm volatile("cp.async.wait_group %0;" :: "n"(n) : "memory")

#define LDSM_X4(r0, r1, r2, r3, a) \
    asm volatile("ldmatrix.sync.aligned.m8n8.x4.shared.b16 {%0,%1,%2,%3}, [%4];" \
        : "=r"(r0), "=r"(r1), "=r"(r2), "=r"(r3) : "r"(a))

#define MMA16816(d, a0, a1, a2, a3, b0, b1) \
    asm volatile("mma.sync.aligned.m16n8k16.row.col.f32.bf16.bf16.f32 " \
        "{%0,%1,%2,%3},{%4,%5,%6,%7},{%8,%9},{%0,%1,%2,%3};" \
        : "+f"((d)[0]), "+f"((d)[1]), "+f"((d)[2]), "+f"((d)[3]) \
        : "r"(a0), "r"(a1), "r"(a2), "r"(a3), "r"(b0), "r"(b1))

// packed f32x2 FMA (base sm_100 feature; compiled fine in round 3)
#define FMA_F32X2(d, a, b) \
    asm("fma.rn.f32x2 %0, %1, %2, %0;" : "+l"(d) : "l"(a), "l"(b))
__device__ __forceinline__ float p2lo(unsigned long long v) {
    return __uint_as_float((unsigned)(v & 0xffffffffull));
}
__device__ __forceinline__ float p2hi(unsigned long long v) {
    return __uint_as_float((unsigned)(v >> 32));
}

// ---------------------------------------------------------------------------
// K1: ex[b,d] = sum_{f,t} input[b,d,f,t] * w_x[f*T+t]; one warp per (b,d)
// ---------------------------------------------------------------------------
__global__ void k1_ex(const float* __restrict__ input, const float* __restrict__ w_attn) {
    const float* w_x = w_attn + 2*HH;
    int warp = (blockIdx.x * blockDim.x + threadIdx.x) >> 5;
    int lane = threadIdx.x & 31;
    if (warp >= BB*DD) return;
    const float* base = input + (size_t)warp * KDIM;
    float s = 0.f;
    #pragma unroll 8
    for (int i = 0; i < KDIM/32; i++) {
        int idx = lane + 32*i;
        s += base[idx] * __ldg(&w_x[idx]);
    }
    #pragma unroll
    for (int o = 16; o > 0; o >>= 1) s += __shfl_down_sync(0xffffffffu, s, o);
    if (lane == 0) g_ex[warp] = s;
}

// ---------------------------------------------------------------------------
// K1b: a[b,:] = softmax(ex[b,:]) over D=128
// ---------------------------------------------------------------------------
__global__ void k1b_softmax() {
    __shared__ float red[4];
    int b = blockIdx.x;
    int d = threadIdx.x;
    int lane = d & 31, w = d >> 5;
    float v = g_ex[b*DD + d];
    float m = v;
    #pragma unroll
    for (int o = 16; o > 0; o >>= 1) m = fmaxf(m, __shfl_xor_sync(0xffffffffu, m, o));
    if (lane == 0) red[w] = m;
    __syncthreads();
    m = fmaxf(fmaxf(red[0], red[1]), fmaxf(red[2], red[3]));
    float e = expf(v - m);
    float s = e;
    #pragma unroll
    for (int o = 16; o > 0; o >>= 1) s += __shfl_xor_sync(0xffffffffu, s, o);
    __syncthreads();
    if (lane == 0) red[w] = s;
    __syncthreads();
    s = red[0] + red[1] + red[2] + red[3];
    g_a[b*DD + d] = e / s;
}

// ---------------------------------------------------------------------------
// kW: split W_ih into bf16 hi/lo, [g][k] K-major
// ---------------------------------------------------------------------------
__global__ void k_wsplit(const float* __restrict__ W_ih) {
    int idx = blockIdx.x * 256 + threadIdx.x;
    if (idx >= G4H*KDIM/2) return;
    float2 v = ((const float2*)W_ih)[idx];
    __nv_bfloat16 h0 = __float2bfloat16(v.x), h1 = __float2bfloat16(v.y);
    __nv_bfloat16 l0 = __float2bfloat16(v.x - __bfloat162float(h0));
    __nv_bfloat16 l1 = __float2bfloat16(v.y - __bfloat162float(h1));
    ((uint32_t*)g_whi)[idx] = (uint32_t)__bfloat16_as_ushort(h0) | ((uint32_t)__bfloat16_as_ushort(h1) << 16);
    ((uint32_t*)g_wlo)[idx] = (uint32_t)__bfloat16_as_ushort(l0) | ((uint32_t)__bfloat16_as_ushort(l1) << 16);
}

// ---------------------------------------------------------------------------
// k_prep: xhat = a[b,k>>3] * input[b,k,t]; bf16 split; transpose to [b][t][k]
// ---------------------------------------------------------------------------
__global__ __launch_bounds__(256) void k_prep(const float* __restrict__ input) {
    __shared__ float tile[64][129];
    int b = blockIdx.y, k0 = blockIdx.x * 64;
    int tid = threadIdx.x;
    int lane = tid & 31, r = tid >> 5;
    #pragma unroll
    for (int it = 0; it < 8; it++) {
        int row = it*8 + r;
        const float4 v = *(const float4*)(input + ((size_t)b*KDIM + k0 + row)*TT + lane*4);
        float s = g_a[b*DD + ((k0 + row) >> 3)];
        tile[row][lane*4+0] = v.x*s;
        tile[row][lane*4+1] = v.y*s;
        tile[row][lane*4+2] = v.z*s;
        tile[row][lane*4+3] = v.w*s;
    }
    __syncthreads();
    int kk = lane * 2;
    #pragma unroll
    for (int it = 0; it < 16; it++) {
        int t = it*8 + r;
        float x0 = tile[kk][t], x1 = tile[kk+1][t];
        __nv_bfloat16 h0 = __float2bfloat16(x0), h1 = __float2bfloat16(x1);
        __nv_bfloat16 l0 = __float2bfloat16(x0 - __bfloat162float(h0));
        __nv_bfloat16 l1 = __float2bfloat16(x1 - __bfloat162float(h1));
        uint32_t hp = (uint32_t)__bfloat16_as_ushort(h0) | ((uint32_t)__bfloat16_as_ushort(h1) << 16);
        uint32_t lp = (uint32_t)__bfloat16_as_ushort(l0) | ((uint32_t)__bfloat16_as_ushort(l1) << 16);
        size_t base = (size_t)(b*TT + t)*(KDIM/2) + (k0 >> 1);
        ((uint32_t*)g_xhi)[base + lane] = hp;
        ((uint32_t*)g_xlo)[base + lane] = lp;
    }
}

// ---------------------------------------------------------------------------
// k2_mma v2: chunk_k=32 (64B rows, SW64), 2-stage cp.async, 2 CTAs/SM.
// CTA: 128t x 128g, 256 threads (8 warps 4x2; warp = 32t x 64g).
// ---------------------------------------------------------------------------
#define S_AHI 0
#define S_ALO 8192
#define S_BHI 16384
#define S_BLO 24576
#define K2_STAGE 32768
#define K2_SMEM (2*K2_STAGE)

__device__ __forceinline__ void k2_load_chunk(uint32_t dstbase, int b, int gbase,
                                              int k0, int tid) {
    const char* pxhi = (const char*)g_xhi;
    const char* pxlo = (const char*)g_xlo;
    const char* pwhi = (const char*)g_whi;
    const char* pwlo = (const char*)g_wlo;
    #pragma unroll
    for (int q = 0; q < 2; q++) {
        int u = tid*2 + q;            // 0..511
        int row = u >> 2, l4 = u & 3;
        uint32_t sw = SWZ64((uint32_t)(row*64 + l4*16));
        size_t aoff = ((size_t)(b*TT + row)*KDIM + k0)*2 + l4*16;
        size_t boff = ((size_t)(gbase + row)*KDIM + k0)*2 + l4*16;
        CP_ASYNC16(dstbase + S_AHI + sw, pxhi + aoff);
        CP_ASYNC16(dstbase + S_ALO + sw, pxlo + aoff);
        CP_ASYNC16(dstbase + S_BHI + sw, pwhi + boff);
        CP_ASYNC16(dstbase + S_BLO + sw, pwlo + boff);
    }
}

__global__ __launch_bounds__(256, 2) void k2_mma() {
    extern __shared__ char smem[];
    uint32_t sb = smem_u32(smem);
    int tid = threadIdx.x;
    int lane = tid & 31, wid = tid >> 5;
    int b = blockIdx.y, gbase = blockIdx.x * 128;
    int wt = wid & 3;        // t block: wt*32
    int wg = wid >> 2;       // g block: wg*64

    float acc[2][8][4];
    #pragma unroll
    for (int mi = 0; mi < 2; mi++)
        #pragma unroll
        for (int ni = 0; ni < 8; ni++)
            #pragma unroll
            for (int q = 0; q < 4; q++) acc[mi][ni][q] = 0.f;

    int a_row_base = wt*32 + (lane & 15);
    int a_col = (lane >> 4) * 16;
    int b_row_base = wg*64 + ((lane >> 4) * 8) + (lane & 7);
    int b_col = ((lane >> 3) & 1) * 16;

    k2_load_chunk(sb, b, gbase, 0, tid);
    CP_COMMIT();

    int buf = 0;
    for (int chunk = 0; chunk < 32; chunk++) {
        if (chunk < 31) {
            k2_load_chunk(sb + (buf ^ 1)*K2_STAGE, b, gbase, (chunk+1)*32, tid);
            CP_COMMIT();
            CP_WAIT(1);
        } else {
            CP_WAIT(0);
        }
        __syncthreads();

        uint32_t base = sb + buf*K2_STAGE;
        #pragma unroll
        for (int ks = 0; ks < 2; ks++) {
            uint32_t ah[2][4], al[2][4];
            #pragma unroll
            for (int mi = 0; mi < 2; mi++) {
                uint32_t off = SWZ64((uint32_t)((a_row_base + mi*16)*64 + ks*32 + a_col));
                LDSM_X4(ah[mi][0], ah[mi][1], ah[mi][2], ah[mi][3], base + S_AHI + off);
                LDSM_X4(al[mi][0], al[mi][1], al[mi][2], al[mi][3], base + S_ALO + off);
            }
            #pragma unroll
            for (int p = 0; p < 4; p++) {
                uint32_t off = SWZ64((uint32_t)((b_row_base + p*16)*64 + ks*32 + b_col));
                uint32_t bh[4], bl[4];
                LDSM_X4(bh[0], bh[1], bh[2], bh[3], base + S_BHI + off);
                LDSM_X4(bl[0], bl[1], bl[2], bl[3], base + S_BLO + off);
                #pragma unroll
                for (int mi = 0; mi < 2; mi++) {
                    #pragma unroll
                    for (int j = 0; j < 2; j++) {
                        int ni = p*2 + j, h = j*2;
                        MMA16816(acc[mi][ni], ah[mi][0], ah[mi][1], ah[mi][2], ah[mi][3],
                                 bh[h], bh[h+1]);
                        MMA16816(acc[mi][ni], ah[mi][0], ah[mi][1], ah[mi][2], ah[mi][3],
                                 bl[h], bl[h+1]);
                        MMA16816(acc[mi][ni], al[mi][0], al[mi][1], al[mi][2], al[mi][3],
                                 bh[h], bh[h+1]);
                    }
                }
            }
        }
        __syncthreads();
        buf ^= 1;
    }

    // Epilogue
    int r0 = wt*32 + (lane >> 2);
    int c0 = gbase + wg*64 + (lane & 3)*2;
    #pragma unroll
    for (int mi = 0; mi < 2; mi++) {
        #pragma unroll
        for (int ni = 0; ni < 8; ni++) {
            int row = r0 + mi*16;
            int col = c0 + ni*8;
            float* p0 = g_y + (size_t)(b*TT + row)*G4H + col;
            float* p1 = g_y + (size_t)(b*TT + row + 8)*G4H + col;
            *(float2*)p0 = make_float2(acc[mi][ni][0], acc[mi][ni][1]);
            *(float2*)p1 = make_float2(acc[mi][ni][2], acc[mi][ni][3]);
        }
    }
}

// ---------------------------------------------------------------------------
// K3: persistent recurrence, f32x2 packed FMA dot products.
// ---------------------------------------------------------------------------
#define WREG 64
#define WP_PITCH 68

__device__ __forceinline__ float sigm(float x) { return 1.f / (1.f + expf(-x)); }

__global__ __launch_bounds__(512, 1) void k3_lstm(const float* __restrict__ W_hh,
                                                  const float* __restrict__ b_ih,
                                                  const float* __restrict__ b_hh,
                                                  float* __restrict__ out) {
    extern __shared__ float sm[];
    float* Wp   = sm;
    float* hs   = Wp + G4H*WP_PITCH;
    float* cs   = hs + 2*HH;
    float* gs   = cs + 2*HH;
    float* bias = gs + 2*G4H;

    int tid = threadIdx.x;
    int b0 = blockIdx.x * 2;
    const int g = tid;

    for (int idx = tid; idx < G4H*(HH-WREG); idx += 512) {
        int gg = idx >> 6;
        int kk = idx & 63;
        Wp[gg*WP_PITCH + kk] = W_hh[(size_t)gg*HH + WREG + kk];
    }
    bias[tid] = b_ih[tid] + b_hh[tid];
    if (tid < 2*HH) { hs[tid] = 0.f; cs[tid] = 0.f; }

    // register half of W row (as packed f32x2 pairs): k in [0,64)
    ulonglong2 wr2[16];
    #pragma unroll
    for (int i = 0; i < 16; i++)
        wr2[i] = *(const ulonglong2*)(W_hh + (size_t)g*HH + 4*i);

    __syncthreads();

    const float myBias = bias[g];
    const float* wprow = Wp + g*WP_PITCH;
    const float* h0 = hs;
    const float* h1 = hs + HH;
    const float* y0p = g_y + ((size_t)b0*TT)*G4H + g;
    const float* y1p = g_y + ((size_t)(b0+1)*TT)*G4H + g;

    float yn0 = *y0p, yn1 = *y1p;

    for (int t = 0; t < TT; t++) {
        float base0 = yn0 + myBias;
        float base1 = yn1 + myBias;
        if (t + 1 < TT) {
            yn0 = y0p[(size_t)(t+1)*G4H];
            yn1 = y1p[(size_t)(t+1)*G4H];
        }
        unsigned long long a0p = 0ull, a0q = 0ull, a1p = 0ull, a1q = 0ull;
        // register-W section: k in [0,64), h reads are warp-broadcasts
        #pragma unroll
        for (int i = 0; i < 16; i++) {
            ulonglong2 w = wr2[i];
            ulonglong2 a = *(const ulonglong2*)(h0 + 4*i);
            ulonglong2 bv = *(const ulonglong2*)(h1 + 4*i);
            FMA_F32X2(a0p, w.x, a.x);
            FMA_F32X2(a0q, w.y, a.y);
            FMA_F32X2(a1p, w.x, bv.x);
            FMA_F32X2(a1q, w.y, bv.y);
        }
        // smem-W section: k in [64,128)
        #pragma unroll
        for (int i = 0; i < 16; i++) {
            ulonglong2 w = *(const ulonglong2*)(wprow + 4*i);
            ulonglong2 a = *(const ulonglong2*)(h0 + WREG + 4*i);
            ulonglong2 bv = *(const ulonglong2*)(h1 + WREG + 4*i);
            FMA_F32X2(a0p, w.x, a.x);
            FMA_F32X2(a0q, w.y, a.y);
            FMA_F32X2(a1p, w.x, bv.x);
            FMA_F32X2(a1q, w.y, bv.y);
        }
        gs[g]       = base0 + p2lo(a0p) + p2hi(a0p) + p2lo(a0q) + p2hi(a0q);
        gs[G4H + g] = base1 + p2lo(a1p) + p2hi(a1p) + p2lo(a1q) + p2hi(a1q);
        __syncthreads();
        if (tid < 2*HH) {
            int bb = tid >> 7;
            int j  = tid & (HH-1);
            const float* G = gs + bb*G4H;
            float iv = G[j], fv = G[HH + j], gv = G[2*HH + j], ov = G[3*HH + j];
            float c  = cs[bb*HH + j];
            float cn = sigm(fv)*c + sigm(iv)*tanhf(gv);
            float hn = sigm(ov)*tanhf(cn);
            cs[bb*HH + j] = cn;
            hs[bb*HH + j] = hn;
            out[((size_t)(b0+bb)*TT + t)*HH + j] = hn;
        }
        __syncthreads();
    }
}

// ---------------------------------------------------------------------------
extern "C" void kernel_launch(void* const* d_in, const int* in_sizes, int n_in,
                              void* d_out, int out_size) {
    const float* input  = (const float*)d_in[0];  // (B,D,F,T)
    const float* w_attn = (const float*)d_in[1];  // (F*T + 2H,)
    // d_in[2] = b_attn (unused: softmax is shift-invariant)
    const float* W_ih   = (const float*)d_in[3];  // (4H, D*F)
    const float* W_hh   = (const float*)d_in[4];  // (4H, H)
    const float* b_ih   = (const float*)d_in[5];  // (4H,)
    const float* b_hh   = (const float*)d_in[6];  // (4H,)
    float* out = (float*)d_out;                   // (B, T, H)

    k1_ex<<<4096, 256>>>(input, w_attn);
    k1b_softmax<<<BB, DD>>>();
    k_wsplit<<<(G4H*KDIM/2 + 255)/256, 256>>>(W_ih);
    {
        dim3 grid(KDIM/64, BB);
        k_prep<<<grid, 256>>>(input);
    }
    {
        cudaFuncSetAttribute(k2_mma, cudaFuncAttributeMaxDynamicSharedMemorySize, K2_SMEM);
        dim3 grid(G4H/128, BB);
        k2_mma<<<grid, 256, K2_SMEM>>>();
    }
    {
        int smem = (G4H*WP_PITCH + 2*HH + 2*HH + 2*G4H + G4H) * (int)sizeof(float);
        cudaFuncSetAttribute(k3_lstm, cudaFuncAttributeMaxDynamicSharedMemorySize, smem);
        k3_lstm<<<BB/2, 512, smem>>>(W_hh, b_ih, b_hh, out);
    }
}